// round 16
// baseline (speedup 1.0000x reference)
#include <cuda_runtime.h>
#include <math.h>

#define B_ 16
#define HW 4096          // 64*64
#define CD 32
#define DIMX 512
#define NSCALES 14
#define NPIX (B_*HW)                 // 65536
#define OUT_ELEMS (B_*DIMX*HW)       // 33554432

#define INV_SQRT32 0.17677669529663687f
#define ACOEF 70.710678118654755f    // 4*100/sqrt(32); p = sigmoid(-ACOEF*z)

__device__ float g_r0[NPIX*CD];      // original projection (token-major)
__device__ float g_r [NPIX*CD];      // residual
__device__ float g_part[4][NPIX*CD]; // split-K partials; [1..3] reused as poolF (scales 7..12)
__device__ float g_pool[94720];      // pooled sums, sliced scales 0..6
__device__ float g_acc[NSCALES][34]; // [0..31]=sum p, [32]=sum H, [33]=sum commit

__constant__ int c_ph[13]   = {1,2,3,4,5,7,9,12,16,21,27,36,48};
__constant__ int c_poff[7]  = {0,512,2560,7168,15360,28160,53248};    // g_pool offsets s<7
__constant__ int c_pfoff[6] = {0,73728,204800,430592,803840,1467392}; // poolF offsets s=7..12
#define SLICED_POOL_FLOATS 94720
#define POOLF_FLOATS 2647040

// ---------------------------------------------------------------- f32x2 helpers
__device__ __forceinline__ unsigned long long pk2(float x, float y) {
    unsigned long long r;
    asm("mov.b64 %0, {%1, %2};" : "=l"(r) : "f"(x), "f"(y));
    return r;
}
__device__ __forceinline__ unsigned long long fma2(unsigned long long a,
                                                   unsigned long long b,
                                                   unsigned long long c) {
    unsigned long long d;
    asm("fma.rn.f32x2 %0, %1, %2, %3;" : "=l"(d) : "l"(a), "l"(b), "l"(c));
    return d;
}
__device__ __forceinline__ void upk2(unsigned long long v, float& lo, float& hi) {
    asm("mov.b64 {%0, %1}, %2;" : "=f"(lo), "=f"(hi) : "l"(v));
}

// ---------------------------------------------------------------- proj_in GEMM (split-K=4, 1 px/thread)
__global__ __launch_bounds__(256) void gemm_in_kernel(
        const float* __restrict__ x, const float* __restrict__ w_in) {
    __shared__ float s_w[128 * CD];
    int tid = threadIdx.x;
    int kc = blockIdx.x & 3;
    int pg = blockIdx.x >> 2;
    const float* wsrc = w_in + kc * 128 * CD;
    for (int i = tid; i < 128 * CD; i += 256) s_w[i] = wsrc[i];
    __syncthreads();

    int px = pg * 256 + tid;
    int b = px >> 12, pl = px & 4095;
    const float* xp = x + (size_t)b * (DIMX * HW) + (size_t)(kc * 128) * HW + pl;

    unsigned long long a[16];
#pragma unroll
    for (int i = 0; i < 16; i++) a[i] = 0ull;

#pragma unroll 8
    for (int c = 0; c < 128; c++) {
        float f = xp[(size_t)c * HW];
        unsigned long long X = pk2(f, f);
        const ulonglong2* row = (const ulonglong2*)(s_w + c * CD);
#pragma unroll
        for (int r = 0; r < 8; r++) {
            ulonglong2 w2 = row[r];
            a[2*r]   = fma2(X, w2.x, a[2*r]);
            a[2*r+1] = fma2(X, w2.y, a[2*r+1]);
        }
    }
    ulonglong2* o = (ulonglong2*)(g_part[kc] + (size_t)px * CD);
#pragma unroll
    for (int k = 0; k < 8; k++) {
        ulonglong2 v; v.x = a[2*k]; v.y = a[2*k+1];
        o[k] = v;
    }
}

// combine: r0 = r = ((p0+p1)+(p2+p3)) + bias ; zeroes g_pool + acc
__global__ __launch_bounds__(256) void combine_kernel(const float* __restrict__ b_in) {
    int idx = blockIdx.x * 256 + threadIdx.x;
    float4 p0 = __ldg((const float4*)g_part[0] + idx);
    float4 p1 = __ldg((const float4*)g_part[1] + idx);
    float4 p2 = __ldg((const float4*)g_part[2] + idx);
    float4 p3 = __ldg((const float4*)g_part[3] + idx);
    float4 bi = __ldg((const float4*)b_in + (idx & 7));
    float4 v;
    v.x = (p0.x + p1.x) + (p2.x + p3.x) + bi.x;
    v.y = (p0.y + p1.y) + (p2.y + p3.y) + bi.y;
    v.z = (p0.z + p1.z) + (p2.z + p3.z) + bi.z;
    v.w = (p0.w + p1.w) + (p2.w + p3.w) + bi.w;
    ((float4*)g_r0)[idx] = v;
    ((float4*)g_r )[idx] = v;

    if (idx < SLICED_POOL_FLOATS) g_pool[idx] = 0.f;
    if (idx < NSCALES * 34) ((float*)g_acc)[idx] = 0.f;
}

// ---------------------------------------------------------------- per-token loss math (lane=d)
__device__ __forceinline__ void loss_token(float ir, float& pa, float& ha, float& ca) {
    float n2 = ir * ir;
#pragma unroll
    for (int o = 16; o > 0; o >>= 1) n2 += __shfl_xor_sync(~0u, n2, o);
    float z = ir / fmaxf(sqrtf(n2), 1e-12f);
    float p = 1.f / (1.f + expf(ACOEF * z));
    float H = -(p * logf(p + 1e-8f) + (1.f - p) * logf(1.f - p + 1e-8f));
    float qv = (z > 0.f) ? INV_SQRT32 : -INV_SQRT32;
    float dz = z - qv;
    pa += p; ha += H; ca += dz * dz;
}

// ---------------------------------------------------------------- pool, scales 0..6 (row x 16px chunks, atomic)
__global__ __launch_bounds__(256) void pool_small_kernel(int s, int S, int Sx) {
    int tid = threadIdx.x, lane = tid & 31;
    int ph = c_ph[s], np = ph * ph, ntok = B_ * np;
    int base = c_poff[s];
    int w = blockIdx.x * 8 + (tid >> 5);
    if (w >= ntok * S * Sx) return;
    int tok = w / (S * Sx);
    int r2 = w - tok * (S * Sx);
    int sy = r2 / Sx, sx = r2 - sy * Sx;
    int b = tok / np, ij = tok - b * np, i = ij / ph, j = ij - i * ph;
    int sh = (i * 64) / ph, eh = ((i + 1) * 64 + ph - 1) / ph;
    int y = sh + sy;
    if (y >= eh) return;
    int sw = (j * 64) / ph, ew = ((j + 1) * 64 + ph - 1) / ph;
    int xs = sw + sx * 16;
    if (xs >= ew) return;
    int xe = min(ew, xs + 16);
    const float* row = g_r + ((size_t)(b * HW + y * 64)) * CD + lane;

    float s0 = 0.f, s1 = 0.f, s2 = 0.f, s3 = 0.f;
    int x = xs;
    for (; x + 8 <= xe; x += 8) {
        float a0 = row[(size_t)(x+0) * CD];
        float a1 = row[(size_t)(x+1) * CD];
        float a2 = row[(size_t)(x+2) * CD];
        float a3 = row[(size_t)(x+3) * CD];
        float a4 = row[(size_t)(x+4) * CD];
        float a5 = row[(size_t)(x+5) * CD];
        float a6 = row[(size_t)(x+6) * CD];
        float a7 = row[(size_t)(x+7) * CD];
        s0 += a0 + a4;
        s1 += a1 + a5;
        s2 += a2 + a6;
        s3 += a3 + a7;
    }
    for (; x < xe; x++) s0 += row[(size_t)x * CD];
    float sum = (s0 + s1) + (s2 + s3);
    atomicAdd(&g_pool[base + tok * CD + lane], sum);
}

// ---------------------------------------------------------------- up: loss(s) preamble + r -= bilerp(sign(pool[s]))
// + (build) atomic accumulation of poolF[s+1]. 16 px/warp (4 px/thread); grid 512.
__global__ __launch_bounds__(256) void up_kernel(int s, int build) {
    __shared__ int s_i0[64], s_i1[64];
    __shared__ float s_f[64];
    __shared__ int s_blo[64], s_bhi[64];
    __shared__ float s_red[34];
    int tid = threadIdx.x, lane = tid & 31;
    int ph = c_ph[s], np = ph * ph;
    int phn = (s < 12) ? c_ph[s + 1] : 0;
    float* poolF = g_part[1];

    if (tid < 64) {
        float src = ((float)tid + 0.5f) * (float)ph * 0.015625f - 0.5f;
        src = fminf(fmaxf(src, 0.f), (float)(ph - 1));
        int i0 = (int)src;
        s_i0[tid] = i0;
        s_i1[tid] = min(i0 + 1, ph - 1);
        s_f[tid]  = src - (float)i0;
        if (build) {
            s_blo[tid] = (tid * phn) >> 6;
            int bh = (((tid + 1) * phn) - 1) >> 6;
            s_bhi[tid] = (bh > phn - 1) ? (phn - 1) : bh;
        }
    }
    if (tid < 34) s_red[tid] = 0.f;
    __syncthreads();

    int gw = blockIdx.x * 8 + (tid >> 5);          // 4096 warps total
    const float* pool = (s < 7) ? (g_pool + c_poff[s]) : (poolF + c_pfoff[s - 7]);

    {   // loss(s) from pool[s]; strided token loop (ntok <= 20736)
        int ntok = B_ * np;
        float pa = 0.f, ha = 0.f, ca = 0.f;
        bool any = false;
        for (int tok = gw; tok < ntok; tok += 4096) {
            any = true;
            int b = tok / np, ij = tok - b * np, i = ij / ph, j = ij - i * ph;
            int ah = ((i + 1) * 64 + ph - 1) / ph - (i * 64) / ph;
            int aw = ((j + 1) * 64 + ph - 1) / ph - (j * 64) / ph;
            float ir = pool[tok * CD + lane] / (float)(ah * aw);
            loss_token(ir, pa, ha, ca);
        }
        if (any) {
#pragma unroll
            for (int o = 16; o > 0; o >>= 1) {
                ha += __shfl_xor_sync(~0u, ha, o);
                ca += __shfl_xor_sync(~0u, ca, o);
            }
            atomicAdd(&s_red[lane], pa);
            if (lane == 0) { atomicAdd(&s_red[32], ha); atomicAdd(&s_red[33], ca); }
        }
    }

    // pixel work: lane = sub(2b)*8 + q(3b); thread handles px = gw*16 + sub + {0,4,8,12}
    int sub = lane >> 3, q = lane & 7;
    int base = gw * 16;
    int npn = phn * phn;
    float* poolN = build ? (poolF + c_pfoff[s + 1 - 7]) : (float*)0;

#pragma unroll
    for (int half = 0; half < 4; half++) {
        int px = base + sub + half * 4;
        int b = px >> 12, h = (px >> 6) & 63, w = px & 63;
        int i0 = s_i0[h], i1 = s_i1[h]; float fh = s_f[h];
        int j0 = s_i0[w], j1 = s_i1[w]; float fw = s_f[w];
        int tb = b * np;
        int t00 = tb + i0 * ph + j0, t01 = tb + i0 * ph + j1;
        int t10 = tb + i1 * ph + j0, t11 = tb + i1 * ph + j1;

        float4 p00 = __ldg((const float4*)(pool + t00 * CD + 4 * q));
        float4 p01 = __ldg((const float4*)(pool + t01 * CD + 4 * q));
        float4 p10 = __ldg((const float4*)(pool + t10 * CD + 4 * q));
        float4 p11 = __ldg((const float4*)(pool + t11 * CD + 4 * q));
        const float* a00 = (const float*)&p00;
        const float* a01 = (const float*)&p01;
        const float* a10 = (const float*)&p10;
        const float* a11 = (const float*)&p11;
        float v[4];
#pragma unroll
        for (int k = 0; k < 4; k++) {
            float s00 = a00[k] > 0.f ? 1.f : -1.f;
            float s01 = a01[k] > 0.f ? 1.f : -1.f;
            float s10 = a10[k] > 0.f ? 1.f : -1.f;
            float s11 = a11[k] > 0.f ? 1.f : -1.f;
            float top = s00 + fw * (s01 - s00);
            float bot = s10 + fw * (s11 - s10);
            v[k] = INV_SQRT32 * (top + fh * (bot - top));
        }

        float4* rp = (float4*)(g_r + (size_t)px * CD + 4 * q);
        float4 rv = *rp;
        rv.x -= v[0]; rv.y -= v[1]; rv.z -= v[2]; rv.w -= v[3];
        *rp = rv;

        if (build) {
            int ilo = s_blo[h], ihi = s_bhi[h];
            int jlo = s_blo[w], jhi = s_bhi[w];
            float* pb = poolN + (size_t)(b * npn) * CD + 4 * q;
            for (int ti = ilo; ti <= ihi; ti++)
                for (int tj = jlo; tj <= jhi; tj++) {
                    float* dst = pb + (ti * phn + tj) * CD;
                    atomicAdd(dst + 0, rv.x);
                    atomicAdd(dst + 1, rv.y);
                    atomicAdd(dst + 2, rv.z);
                    atomicAdd(dst + 3, rv.w);
                }
        }
    }

    __syncthreads();
    if (tid < 34) atomicAdd(&g_acc[s][tid], s_red[tid]);
}

// ---------------------------------------------------------------- up(12): loss(12) preamble + up + fused loss13; grid 1024
__global__ __launch_bounds__(256) void up12_kernel() {
    __shared__ int s_i0[64], s_i1[64];
    __shared__ float s_f[64];
    __shared__ float s_12[34];
    __shared__ float s_13[34];
    int tid = threadIdx.x, lane = tid & 31;
    const int ph = 48, np = 48 * 48;
    const float* pool = g_part[1] + c_pfoff[5];   // poolF[12]

    if (tid < 64) {
        float src = ((float)tid + 0.5f) * 48.f * 0.015625f - 0.5f;
        src = fminf(fmaxf(src, 0.f), 47.f);
        int i0 = (int)src;
        s_i0[tid] = i0;
        s_i1[tid] = min(i0 + 1, 47);
        s_f[tid]  = src - (float)i0;
    }
    if (tid < 34) { s_12[tid] = 0.f; s_13[tid] = 0.f; }
    __syncthreads();

    int gw = blockIdx.x * 8 + (tid >> 5);     // 8192 warps

    {   // loss(12): ntok = 36864, 5 iterations
        float pa = 0.f, ha = 0.f, ca = 0.f;
        for (int tok = gw; tok < B_ * np; tok += 8192) {
            int b = tok / np, ij = tok - b * np, i = ij / ph, j = ij - i * ph;
            int ah = ((i + 1) * 64 + ph - 1) / ph - (i * 64) / ph;
            int aw = ((j + 1) * 64 + ph - 1) / ph - (j * 64) / ph;
            float ir = pool[tok * CD + lane] / (float)(ah * aw);
            loss_token(ir, pa, ha, ca);
        }
#pragma unroll
        for (int o = 16; o > 0; o >>= 1) {
            ha += __shfl_xor_sync(~0u, ha, o);
            ca += __shfl_xor_sync(~0u, ca, o);
        }
        atomicAdd(&s_12[lane], pa);
        if (lane == 0) { atomicAdd(&s_12[32], ha); atomicAdd(&s_12[33], ca); }
    }

    int sub = lane >> 3, q = lane & 7;
    float pv[4] = {0.f, 0.f, 0.f, 0.f};
    float ha = 0.f, ca = 0.f;
#pragma unroll
    for (int half = 0; half < 2; half++) {
        int px = gw * 8 + sub + half * 4;
        int b = px >> 12, h = (px >> 6) & 63, w = px & 63;
        int i0 = s_i0[h], i1 = s_i1[h]; float fh = s_f[h];
        int j0 = s_i0[w], j1 = s_i1[w]; float fw = s_f[w];
        int tb = b * np;
        float4 p00 = __ldg((const float4*)(pool + (tb + i0 * ph + j0) * CD + 4 * q));
        float4 p01 = __ldg((const float4*)(pool + (tb + i0 * ph + j1) * CD + 4 * q));
        float4 p10 = __ldg((const float4*)(pool + (tb + i1 * ph + j0) * CD + 4 * q));
        float4 p11 = __ldg((const float4*)(pool + (tb + i1 * ph + j1) * CD + 4 * q));
        const float* a00 = (const float*)&p00;
        const float* a01 = (const float*)&p01;
        const float* a10 = (const float*)&p10;
        const float* a11 = (const float*)&p11;

        float4* rp = (float4*)(g_r + (size_t)px * CD + 4 * q);
        float4 rv = *rp;
        float* rvp = (float*)&rv;
#pragma unroll
        for (int k = 0; k < 4; k++) {
            float s00 = a00[k] > 0.f ? 1.f : -1.f;
            float s01 = a01[k] > 0.f ? 1.f : -1.f;
            float s10 = a10[k] > 0.f ? 1.f : -1.f;
            float s11 = a11[k] > 0.f ? 1.f : -1.f;
            float top = s00 + fw * (s01 - s00);
            float bot = s10 + fw * (s11 - s10);
            rvp[k] -= INV_SQRT32 * (top + fh * (bot - top));
        }
        *rp = rv;

        float n2 = rv.x*rv.x + rv.y*rv.y + rv.z*rv.z + rv.w*rv.w;
        n2 += __shfl_xor_sync(~0u, n2, 1);
        n2 += __shfl_xor_sync(~0u, n2, 2);
        n2 += __shfl_xor_sync(~0u, n2, 4);
        float inv = 1.f / fmaxf(sqrtf(n2), 1e-12f);
#pragma unroll
        for (int k = 0; k < 4; k++) {
            float z = rvp[k] * inv;
            float p = 1.f / (1.f + expf(ACOEF * z));
            ha += -(p * logf(p + 1e-8f) + (1.f - p) * logf(1.f - p + 1e-8f));
            float qv = (z > 0.f) ? INV_SQRT32 : -INV_SQRT32;
            float dz = z - qv;
            ca += dz * dz;
            pv[k] += p;
        }
    }

    atomicAdd(&s_13[4*q+0], pv[0]);
    atomicAdd(&s_13[4*q+1], pv[1]);
    atomicAdd(&s_13[4*q+2], pv[2]);
    atomicAdd(&s_13[4*q+3], pv[3]);
#pragma unroll
    for (int o = 16; o > 0; o >>= 1) {
        ha += __shfl_xor_sync(~0u, ha, o);
        ca += __shfl_xor_sync(~0u, ca, o);
    }
    if (lane == 0) { atomicAdd(&s_13[32], ha); atomicAdd(&s_13[33], ca); }

    __syncthreads();
    if (tid < 34) {
        atomicAdd(&g_acc[12][tid], s_12[tid]);
        atomicAdd(&g_acc[13][tid], s_13[tid]);
    }
}

// ---------------------------------------------------------------- finalize losses
__global__ void finalize_kernel(float* __restrict__ loss_out) {
    int s = threadIdx.x >> 5;
    int lane = threadIdx.x & 31;
    if (s >= NSCALES) return;
    int ph = (s < 13) ? c_ph[s] : 64;
    float n = (float)(B_ * ph * ph);
    float ap = g_acc[s][lane] / n;
    float H = -(ap * logf(ap + 1e-8f) + (1.f - ap) * logf(1.f - ap + 1e-8f));
#pragma unroll
    for (int o = 16; o > 0; o >>= 1) H += __shfl_xor_sync(~0u, H, o);
    if (lane == 0) {
        float ps = g_acc[s][32] / n;
        float cm = g_acc[s][33] / (n * 32.f);
        loss_out[s] = (ps - H) * (0.1f / 100.f) + 0.25f * cm;
    }
}

// ---------------------------------------------------------------- proj_out GEMM (split-N=4, 1 px/thread)
__global__ __launch_bounds__(256) void gemm_out_kernel(
        const float* __restrict__ w_out,
        const float* __restrict__ b_out,
        float* __restrict__ out) {
    __shared__ float s_wt[128 * 36];
    __shared__ float s_b[128];
    int tid = threadIdx.x;
    int kc = blockIdx.x & 3;
    int pg = blockIdx.x >> 2;
    int c0 = kc * 128;
    for (int i = tid; i < 128 * CD; i += 256) {
        int d = i >> 7, c = i & 127;
        s_wt[c * 36 + d] = w_out[d * DIMX + c0 + c];
    }
    if (tid < 128) s_b[tid] = b_out[c0 + tid];
    __syncthreads();

    int px = pg * 256 + tid;
    int b = px >> 12, pl = px & 4095;
    size_t o = (size_t)px * CD;

    unsigned long long Q[16];
#pragma unroll
    for (int k = 0; k < 8; k++) {
        float4 a = __ldg((const float4*)(g_r0 + o) + k);
        float4 r = ((const float4*)(g_r + o))[k];
        float qx = (r.x > 0.f) ? INV_SQRT32 : -INV_SQRT32;
        float qy = (r.y > 0.f) ? INV_SQRT32 : -INV_SQRT32;
        float qz = (r.z > 0.f) ? INV_SQRT32 : -INV_SQRT32;
        float qw = (r.w > 0.f) ? INV_SQRT32 : -INV_SQRT32;
        Q[2*k]   = pk2(a.x - r.x + qx, a.y - r.y + qy);
        Q[2*k+1] = pk2(a.z - r.z + qz, a.w - r.w + qw);
    }

    float* op = out + (size_t)b * (DIMX * HW) + (size_t)c0 * HW + pl;
#pragma unroll 2
    for (int c = 0; c < 128; c++) {
        const ulonglong2* wrow = (const ulonglong2*)(s_wt + c * 36);
        unsigned long long ae = 0, ao = 0;
#pragma unroll
        for (int r = 0; r < 8; r++) {
            ulonglong2 W = wrow[r];
            ae = fma2(Q[2*r],   W.x, ae);
            ao = fma2(Q[2*r+1], W.y, ao);
        }
        float lo, hi, sum;
        upk2(ae, lo, hi); sum = lo + hi;
        upk2(ao, lo, hi); sum += lo + hi;
        op[(size_t)c * HW] = sum + s_b[c];
    }
}

// ---------------------------------------------------------------- launch
extern "C" void kernel_launch(void* const* d_in, const int* in_sizes, int n_in,
                              void* d_out, int out_size) {
    const float* x     = (const float*)d_in[0];
    const float* w_in  = (const float*)d_in[1];
    const float* b_in  = (const float*)d_in[2];
    const float* w_out = (const float*)d_in[3];
    const float* b_out = (const float*)d_in[4];
    float* out = (float*)d_out;

    static const int sched[13] = {1,2,3,4,5,7,9,12,16,21,27,36,48};
    static const int SxT[7]    = {4,2,2,1,1,1,1};   // 16px x-chunks for ph 1,2,3,4,5,7,9

    gemm_in_kernel<<<1024, 256>>>(x, w_in);
    combine_kernel<<<2048, 256>>>(b_in);            // also zeroes g_pool + acc

    // zero poolF (scales 7..12) inside g_part[1..]
    void* gp = 0;
    cudaGetSymbolAddress(&gp, g_part);
    cudaMemsetAsync((char*)gp + (size_t)NPIX * CD * sizeof(float), 0,
                    (size_t)POOLF_FLOATS * sizeof(float));

    // s = 0..6: deterministic sliced pools + up (up(6) starts building poolF[7])
    for (int s = 0; s < 7; s++) {
        int ph = sched[s];
        int ntok = B_ * ph * ph;
        int S = 64 / ph + 2;
        int Sx = SxT[s];
        int work = ntok * S * Sx;
        pool_small_kernel<<<(work + 7) / 8, 256>>>(s, S, Sx);
        up_kernel<<<512, 256>>>(s, s >= 6 ? 1 : 0);
    }
    // s = 7..11: fused loss(s) + up(s) + build poolF[s+1]
    for (int s = 7; s < 12; s++)
        up_kernel<<<512, 256>>>(s, 1);
    // s = 12: loss(12) + up + fused loss13
    up12_kernel<<<1024, 256>>>();

    if (out_size >= OUT_ELEMS + NSCALES)
        finalize_kernel<<<1, NSCALES * 32>>>(out + OUT_ELEMS);
    gemm_out_kernel<<<1024, 256>>>(w_out, b_out, out);
}